// round 8
// baseline (speedup 1.0000x reference)
#include <cuda_runtime.h>
#include <cuda_bf16.h>
#include <math.h>
#include <stdint.h>

#define DIMK   256
#define LATENT 1024
#define BB     128
#define TT     512
#define KB     2048          // B' (scan) columns: [hi | lo]
#define NCTA   128

// ---------------------------------------------------------------------------
// Scratch (__device__ globals — no allocations allowed)
// ---------------------------------------------------------------------------
__device__ __nv_bfloat16 g_B[LATENT * KB];              // scan B' = WhT split [n][hi1024|lo1024]
// scan A in MMA-fragment layout: [ping][(half*8+mfrag)*2048 + s*32 + lane] of uint4 (4 regs)
__device__ uint4 g_Af[2][2 * 8 * 64 * 32];
__device__ __nv_bfloat16 g_X[(size_t)BB * TT * 512];    // gemm1 A' = x split [r][hi256|lo256]
__device__ __nv_bfloat16 g_BX[LATENT * 512];            // gemm1 B' = WxT split [n][hi256|lo256]
__device__ unsigned g_bar_count;

__device__ __forceinline__ uint32_t smem_u32(const void* p) {
    uint32_t a;
    asm("{ .reg .u64 t; cvta.to.shared.u64 t, %1; cvt.u32.u64 %0, t; }" : "=r"(a) : "l"(p));
    return a;
}
__device__ __forceinline__ void cp16(uint32_t dst, const void* src) {
    asm volatile("cp.async.cg.shared.global [%0], [%1], 16;" :: "r"(dst), "l"(src));
}
__device__ __forceinline__ uint4 ldg_cg(const uint4* p) {
    uint4 v;
    asm volatile("ld.global.cg.v4.u32 {%0,%1,%2,%3}, [%4];"
                 : "=r"(v.x), "=r"(v.y), "=r"(v.z), "=r"(v.w) : "l"(p));
    return v;
}
__device__ __forceinline__ uint32_t pack_hi(float a, float b) {
    __nv_bfloat162 h; h.x = __float2bfloat16(a); h.y = __float2bfloat16(b);
    return *reinterpret_cast<uint32_t*>(&h);
}
__device__ __forceinline__ uint32_t pack_lo(float a, float b) {
    __nv_bfloat16 ha = __float2bfloat16(a), hb = __float2bfloat16(b);
    __nv_bfloat162 l;
    l.x = __float2bfloat16(a - __bfloat162float(ha));
    l.y = __float2bfloat16(b - __bfloat162float(hb));
    return *reinterpret_cast<uint32_t*>(&l);
}
#define CP_COMMIT() asm volatile("cp.async.commit_group;")
#define CP_WAIT(n)  asm volatile("cp.async.wait_group %0;" :: "n"(n))

#define LDSM4(r0, r1, r2, r3, addr) \
    asm volatile("ldmatrix.sync.aligned.m8n8.x4.shared.b16 {%0,%1,%2,%3}, [%4];" \
                 : "=r"(r0), "=r"(r1), "=r"(r2), "=r"(r3) : "r"(addr))
#define MMA16816(d, a0, a1, a2, a3, b0, b1) \
    asm volatile("mma.sync.aligned.m16n8k16.row.col.f32.bf16.bf16.f32 " \
                 "{%0,%1,%2,%3}, {%4,%5,%6,%7}, {%8,%9}, {%0,%1,%2,%3};" \
                 : "+f"((d)[0]), "+f"((d)[1]), "+f"((d)[2]), "+f"((d)[3]) \
                 : "r"(a0), "r"(a1), "r"(a2), "r"(a3), "r"(b0), "r"(b1))

// ---------------------------------------------------------------------------
// prep: Wh[k][n] -> g_B[n][k]=hi, g_B[n][1024+k]=lo
// ---------------------------------------------------------------------------
__global__ void prep_wh_kernel(const float* __restrict__ W) {
    const float* Wh = W + (size_t)DIMK * LATENT;
    __shared__ float tile[32][33];
    int bx = blockIdx.x * 32;
    int by = blockIdx.y * 32;
    int tx = threadIdx.x, ty = threadIdx.y;
    #pragma unroll
    for (int i = ty; i < 32; i += 8)
        tile[i][tx] = Wh[(size_t)(by + i) * LATENT + bx + tx];
    __syncthreads();
    #pragma unroll
    for (int i = ty; i < 32; i += 8) {
        float v = tile[tx][i];
        size_t o = (size_t)(bx + i) * KB + by + tx;
        __nv_bfloat16 h = __float2bfloat16(v);
        g_B[o]        = h;
        g_B[o + 1024] = __float2bfloat16(v - __bfloat162float(h));
    }
}

// ---------------------------------------------------------------------------
// prep: Wx[k][n] (k<256) -> g_BX[n][k]=hi, [n][256+k]=lo
// ---------------------------------------------------------------------------
__global__ void prep_bx_kernel(const float* __restrict__ W) {
    __shared__ float tile[32][33];
    int bx = blockIdx.x * 32;
    int by = blockIdx.y * 32;
    int tx = threadIdx.x, ty = threadIdx.y;
    #pragma unroll
    for (int i = ty; i < 32; i += 8)
        tile[i][tx] = W[(size_t)(by + i) * LATENT + bx + tx];
    __syncthreads();
    #pragma unroll
    for (int i = ty; i < 32; i += 8) {
        float v = tile[tx][i];
        size_t o = (size_t)(bx + i) * 512 + by + tx;
        __nv_bfloat16 h = __float2bfloat16(v);
        g_BX[o]       = h;
        g_BX[o + 256] = __float2bfloat16(v - __bfloat162float(h));
    }
}

// ---------------------------------------------------------------------------
// prep: x[r][d] fp32 -> g_X[r][d]=hi, g_X[r][256+d]=lo  (r = b*T + t)
// ---------------------------------------------------------------------------
__global__ void prep_x_kernel(const float* __restrict__ x) {
    size_t idx = (size_t)blockIdx.x * 256 + threadIdx.x;
    size_t e = idx * 4;
    size_t r = e >> 8;
    int d = (int)(e & 255);
    float4 v = *reinterpret_cast<const float4*>(x + e);
    size_t o = r * 512 + d;
    *reinterpret_cast<uint32_t*>(&g_X[o + 0])   = pack_hi(v.x, v.y);
    *reinterpret_cast<uint32_t*>(&g_X[o + 2])   = pack_hi(v.z, v.w);
    *reinterpret_cast<uint32_t*>(&g_X[o + 256]) = pack_lo(v.x, v.y);
    *reinterpret_cast<uint32_t*>(&g_X[o + 258]) = pack_lo(v.z, v.w);
}

// ---------------------------------------------------------------------------
// GEMM1 (tensor): out[t,b,:] = x @ Wx + b.  CTA 128 rows, warp tile 32x32
// (4m x 2n warps). A resident 128KB, B double-buffered 2x16KB. 1 CTA/SM.
// ---------------------------------------------------------------------------
#define G1_SMB   131072
#define G1_SMEM  (131072 + 2 * 16384)

__global__ void __launch_bounds__(256, 1)
gemm1_mma_kernel(const float* __restrict__ bias, float* __restrict__ out) {
    extern __shared__ char smem[];
    const uint32_t smA = smem_u32(smem);
    const uint32_t smB = smA + G1_SMB;
    const int tid = threadIdx.x;
    const int lid = tid & 31;
    const int wid = tid >> 5;
    const int r0 = blockIdx.x * 128;

    // resident A': 128 rows x 512 cols bf16 = 128KB (4 chunks of 32KB)
    {
        const __nv_bfloat16* gA = g_X + (size_t)r0 * 512;
        #pragma unroll
        for (int j = 0; j < 32; ++j) {
            int ci = tid + j * 256;
            int ch = ci >> 11;
            int rem = ci & 2047;
            int rw = rem >> 4;
            int cc = rem & 15;
            cp16(smA + ch * 32768 + rw * 256 + (((cc ^ (rw & 15))) << 4),
                 gA + (size_t)rw * 512 + ch * 128 + cc * 8);
        }
        CP_COMMIT();
    }
    // stage B chunk gg=0
    {
        #pragma unroll
        for (int j = 0; j < 4; ++j) {
            int ci = tid + j * 256;
            int rw = ci >> 4;
            int cc = ci & 15;
            cp16(smB + rw * 256 + (((cc ^ (rw & 15))) << 4),
                 g_BX + (size_t)rw * 512 + cc * 8);
        }
        CP_COMMIT();
    }

    const int wm = wid >> 1;            // 0..3 (32-row tiles)
    const int wn = wid & 1;             // 0..1 (32-col tiles)
    const int a_row0 = wm * 32 + (lid & 15);
    const int a_row1 = a_row0 + 16;
    const int a_kh   = (lid >> 4) & 1;
    const int b_r    = (((lid >> 4) & 1) << 3) + (lid & 7);
    const int b_row0 = wn * 32 + b_r;
    const int b_row1 = b_row0 + 16;
    const int b_kh   = (lid >> 3) & 1;
    const int a_swz0 = a_row0 & 15, a_swz1 = a_row1 & 15;
    const int b_swz0 = b_row0 & 15, b_swz1 = b_row1 & 15;
    const int g8 = lid >> 2;
    const int q  = lid & 3;

    float acc[8][4];

    #pragma unroll 1
    for (int gg = 0; gg < 96; ++gg) {
        const int nt = gg / 6;
        const int c  = gg % 6;

        if (gg + 1 < 96) {
            const int nt2 = (gg + 1) / 6;
            const int c2  = (gg + 1) % 6;
            const int cb  = (c2 & 3) * 128;        // B col map: hi0,hi1,lo0,lo1,hi0,hi1
            uint32_t dst = smB + ((gg + 1) & 1) * 16384;
            const __nv_bfloat16* gBn = g_BX + (size_t)(nt2 * 64) * 512;
            #pragma unroll
            for (int j = 0; j < 4; ++j) {
                int ci = tid + j * 256;
                int rw = ci >> 4;
                int cc = ci & 15;
                cp16(dst + rw * 256 + (((cc ^ (rw & 15))) << 4),
                     gBn + (size_t)rw * 512 + cb + cc * 8);
            }
            CP_COMMIT();
            CP_WAIT(1);
        } else {
            CP_WAIT(0);
        }
        __syncthreads();

        if (c == 0) {
            #pragma unroll
            for (int i = 0; i < 8; ++i)
                #pragma unroll
                for (int j = 0; j < 4; ++j) acc[i][j] = 0.f;
        }

        const int ach = (c < 2) ? c : c - 2;       // A chunk: 0,1,0,1,2,3
        const uint32_t aR0 = smA + ach * 32768 + a_row0 * 256;
        const uint32_t aR1 = smA + ach * 32768 + a_row1 * 256;
        const uint32_t bR0 = smB + (gg & 1) * 16384 + b_row0 * 256;
        const uint32_t bR1 = smB + (gg & 1) * 16384 + b_row1 * 256;

        #pragma unroll
        for (int s = 0; s < 8; ++s) {
            uint32_t A0, A1, A2, A3, C0, C1, C2, C3;
            uint32_t B[8];
            LDSM4(A0, A1, A2, A3, aR0 + (((2 * s + a_kh) ^ a_swz0) << 4));
            LDSM4(C0, C1, C2, C3, aR1 + (((2 * s + a_kh) ^ a_swz1) << 4));
            LDSM4(B[0], B[1], B[2], B[3], bR0 + (((2 * s + b_kh) ^ b_swz0) << 4));
            LDSM4(B[4], B[5], B[6], B[7], bR1 + (((2 * s + b_kh) ^ b_swz1) << 4));
            #pragma unroll
            for (int ni = 0; ni < 4; ++ni) {
                MMA16816(acc[ni],     A0, A1, A2, A3, B[ni * 2], B[ni * 2 + 1]);
                MMA16816(acc[4 + ni], C0, C1, C2, C3, B[ni * 2], B[ni * 2 + 1]);
            }
        }

        if (c == 5) {
            const int n0t = nt * 64;
            #pragma unroll
            for (int mi = 0; mi < 2; ++mi) {
                #pragma unroll
                for (int ni = 0; ni < 4; ++ni) {
                    const int col = n0t + wn * 32 + ni * 8 + q * 2;
                    float2 bv = *reinterpret_cast<const float2*>(bias + col);
                    #pragma unroll
                    for (int rh = 0; rh < 2; ++rh) {
                        const int r = r0 + wm * 32 + mi * 16 + g8 + rh * 8;
                        const int bi = r >> 9;
                        const int ti = r & (TT - 1);
                        float2 o;
                        o.x = acc[mi * 4 + ni][rh * 2 + 0] + bv.x;
                        o.y = acc[mi * 4 + ni][rh * 2 + 1] + bv.y;
                        *reinterpret_cast<float2*>(
                            &out[((size_t)ti * BB + bi) * LATENT + col]) = o;
                    }
                }
            }
        }
        __syncthreads();
    }
}

// ---------------------------------------------------------------------------
// t = 0: out[0] = tanh(out[0]); write h0 into g_Af[0] (fragment layout)
// ---------------------------------------------------------------------------
__global__ void tanh0_kernel(float* __restrict__ out0) {
    int i = blockIdx.x * blockDim.x + threadIdx.x;    // 0..65535
    if (i == 0) g_bar_count = 0;
    int m = i >> 9;          // row 0..127
    int p = i & 511;         // bf16 pair 0..511 (k = 2p)
    float2 v = *reinterpret_cast<const float2*>(out0 + (size_t)m * LATENT + p * 2);
    float v0 = tanhf(v.x), v1 = tanhf(v.y);
    float2 ov; ov.x = v0; ov.y = v1;
    *reinterpret_cast<float2*>(out0 + (size_t)m * LATENT + p * 2) = ov;

    const int mf = m >> 4, fr = m & 15;
    const int s = p >> 3;
    const int lane = (fr & 7) * 4 + (p & 3);
    const int reg = (fr >> 3) + ((p >> 2) & 1) * 2;
    uint32_t* Aw = reinterpret_cast<uint32_t*>(g_Af[0]);
    Aw[((mf * 64 + s) * 32 + lane) * 4 + reg]       = pack_hi(v0, v1);
    Aw[(((8 + mf) * 64 + s) * 32 + lane) * 4 + reg] = pack_lo(v0, v1);
}

// ---------------------------------------------------------------------------
// Persistent scan: 128 CTAs (4m x 32n tiles of 32x32), 256 threads = 8 warps.
// 8-way split-K: warp w owns k-chunk w (128 cols), computes the FULL 32x32
// tile for all 3 terms. A fragments loaded straight from global (ld.global.cg,
// fragment layout, double-buffered over s) — A never touches smem. B' (hi+lo,
// 128KB) resident in smem. Reduction of 8 partials in smem, fused tanh
// epilogue writes out + next A-fragment buffer. Grid barrier per step.
// ---------------------------------------------------------------------------
#define SCAN_SMB  131072                       // B: hi 8 chunks x 8KB, lo at +65536
#define SCAN_PART 131072                       // partials: 8 warps x 4608B
#define SMEM_SCAN (131072 + 8 * 4608)          // 167936

__global__ void __launch_bounds__(256, 1)
scan_kernel(float* __restrict__ out) {
    extern __shared__ char smem[];
    const int tid = threadIdx.x;
    const int lid = tid & 31;
    const int wid = tid >> 5;
    const int bid = blockIdx.x;
    const int m0 = (bid & 3) * 32;
    const int n0 = (bid >> 2) * 32;
    const uint32_t smB = smem_u32(smem);

    // ---- resident B': 8192 cp16, 32/thread ----
    {
        const __nv_bfloat16* gB = g_B + (size_t)n0 * KB;
        #pragma unroll
        for (int j = 0; j < 32; ++j) {
            int ci = tid + j * 256;
            int half = ci >> 12;
            int rem = ci & 4095;
            int ch = rem >> 9;
            int rw = (rem >> 4) & 31;
            int cc = rem & 15;
            cp16(smB + half * 65536 + ch * 8192 + rw * 256 + (((cc ^ (rw & 15))) << 4),
                 gB + (size_t)rw * KB + half * 1024 + ch * 128 + cc * 8);
        }
        CP_COMMIT();
        CP_WAIT(0);
        __syncthreads();
    }

    // ---- B ldmatrix geometry (this warp's chunk = wid) ----
    const int b_r  = (((lid >> 4) & 1) << 3) + (lid & 7);
    const int b_kh = (lid >> 3) & 1;
    const int b_swz0 = b_r & 15;                    // same for row and row+16
    const uint32_t bH0 = smB + wid * 8192 + b_r * 256;
    const uint32_t bH1 = bH0 + 16 * 256;
    const uint32_t bL0 = bH0 + 65536;
    const uint32_t bL1 = bH1 + 65536;

    const int mf0 = m0 >> 4;
    const int wbase = wid * 8;

    // ---- epilogue geometry ----
    const int e_row = tid >> 3;            // 0..31
    const int e_cg  = (tid & 7) * 4;       // 0..28
    const int gm = m0 + e_row;
    const int fr = gm & 15;
    const int wmf = gm >> 4;
    const int e0 = n0 + e_cg;              // global k for A'
    const int ws = e0 >> 4;
    const int wlane = (fr & 7) * 4 + ((e0 & 7) >> 1);
    const int wreg  = (fr >> 3) + (((e0 >> 3) & 1) << 1);
    const int widx_hi = ((wmf * 64 + ws) * 32 + wlane) * 4 + wreg;
    const int widx_lo = (((8 + wmf) * 64 + ws) * 32 + wlane) * 4 + wreg;

    for (int t = 1; t < TT; ++t) {
        const int rp = (t - 1) & 1;
        const uint4* Ar = g_Af[rp];
        uint32_t* Aw = reinterpret_cast<uint32_t*>(g_Af[rp ^ 1]);
        float* out_t = out + (size_t)t * BB * LATENT;

        // xw prefetch (DRAM latency hidden under k-loop)
        const float4 xv = *reinterpret_cast<const float4*>(
            out_t + (size_t)gm * LATENT + e0);

        // A fragment double-buffer (hi + lo, 2 m-frags each)
        uint4 ahv[2][2], alv[2][2];
        {
            const int sg = wbase;
            ahv[0][0] = ldg_cg(Ar + (mf0 + 0) * 2048 + sg * 32 + lid);
            ahv[0][1] = ldg_cg(Ar + (mf0 + 1) * 2048 + sg * 32 + lid);
            alv[0][0] = ldg_cg(Ar + (mf0 + 8) * 2048 + sg * 32 + lid);
            alv[0][1] = ldg_cg(Ar + (mf0 + 9) * 2048 + sg * 32 + lid);
        }

        float acc[32];
        #pragma unroll
        for (int i = 0; i < 32; ++i) acc[i] = 0.f;

        #pragma unroll
        for (int si = 0; si < 8; ++si) {
            if (si < 7) {
                const int sg = wbase + si + 1;
                const int nb = (si + 1) & 1;
                ahv[nb][0] = ldg_cg(Ar + (mf0 + 0) * 2048 + sg * 32 + lid);
                ahv[nb][1] = ldg_cg(Ar + (mf0 + 1) * 2048 + sg * 32 + lid);
                alv[nb][0] = ldg_cg(Ar + (mf0 + 8) * 2048 + sg * 32 + lid);
                alv[nb][1] = ldg_cg(Ar + (mf0 + 9) * 2048 + sg * 32 + lid);
            }
            const uint32_t off = ((uint32_t)((2 * si + b_kh) ^ b_swz0)) << 4;
            uint32_t bh[8], bl[8];
            LDSM4(bh[0], bh[1], bh[2], bh[3], bH0 + off);
            LDSM4(bh[4], bh[5], bh[6], bh[7], bH1 + off);
            LDSM4(bl[0], bl[1], bl[2], bl[3], bL0 + off);
            LDSM4(bl[4], bl[5], bl[6], bl[7], bL1 + off);

            const uint4 AH0 = ahv[si & 1][0], AH1 = ahv[si & 1][1];
            const uint4 AL0 = alv[si & 1][0], AL1 = alv[si & 1][1];

            #pragma unroll
            for (int ni = 0; ni < 4; ++ni) {
                MMA16816(acc + ni * 4, AH0.x, AH0.y, AH0.z, AH0.w, bh[ni * 2], bh[ni * 2 + 1]);
                MMA16816(acc + ni * 4, AH0.x, AH0.y, AH0.z, AH0.w, bl[ni * 2], bl[ni * 2 + 1]);
                MMA16816(acc + ni * 4, AL0.x, AL0.y, AL0.z, AL0.w, bh[ni * 2], bh[ni * 2 + 1]);
                MMA16816(acc + 16 + ni * 4, AH1.x, AH1.y, AH1.z, AH1.w, bh[ni * 2], bh[ni * 2 + 1]);
                MMA16816(acc + 16 + ni * 4, AH1.x, AH1.y, AH1.z, AH1.w, bl[ni * 2], bl[ni * 2 + 1]);
                MMA16816(acc + 16 + ni * 4, AL1.x, AL1.y, AL1.z, AL1.w, bh[ni * 2], bh[ni * 2 + 1]);
            }
        }

        // ---- write this warp's 32x32 partial (stride-36 words, conflict-light) ----
        {
            char* pb = smem + SCAN_PART + wid * 4608;
            #pragma unroll
            for (int mi = 0; mi < 2; ++mi)
                #pragma unroll
                for (int ni = 0; ni < 4; ++ni)
                    #pragma unroll
                    for (int rh = 0; rh < 2; ++rh) {
                        const int r_l = mi * 16 + (lid >> 2) + rh * 8;
                        const int c_l = ni * 8 + (lid & 3) * 2;
                        float2 pv;
                        pv.x = acc[mi * 16 + ni * 4 + rh * 2 + 0];
                        pv.y = acc[mi * 16 + ni * 4 + rh * 2 + 1];
                        *reinterpret_cast<float2*>(pb + (r_l * 36 + c_l) * 4) = pv;
                    }
        }
        __syncthreads();

        // ---- reduce 8 partials + tanh + store out + next A-frag buffer ----
        {
            float4 s4 = xv;
            #pragma unroll
            for (int w = 0; w < 8; ++w) {
                const float4 pv = *reinterpret_cast<const float4*>(
                    smem + SCAN_PART + w * 4608 + (e_row * 36 + e_cg) * 4);
                s4.x += pv.x; s4.y += pv.y; s4.z += pv.z; s4.w += pv.w;
            }
            float4 r;
            r.x = tanhf(s4.x);
            r.y = tanhf(s4.y);
            r.z = tanhf(s4.z);
            r.w = tanhf(s4.w);
            *reinterpret_cast<float4*>(out_t + (size_t)gm * LATENT + e0) = r;

            Aw[widx_hi]     = pack_hi(r.x, r.y);
            Aw[widx_hi + 4] = pack_hi(r.z, r.w);   // next lane = +4 words
            Aw[widx_lo]     = pack_lo(r.x, r.y);
            Aw[widx_lo + 4] = pack_lo(r.z, r.w);
        }

        // ---- grid barrier: RED + count poll ----
        if (t + 1 < TT) {
            __threadfence();
            __syncthreads();
            if (tid == 0) {
                atomicAdd(&g_bar_count, 1u);
                const unsigned target = (unsigned)t * NCTA;
                while (*(volatile unsigned*)&g_bar_count < target) { }
            }
            __syncthreads();
        }
    }
}

// ---------------------------------------------------------------------------
extern "C" void kernel_launch(void* const* d_in, const int* in_sizes, int n_in,
                              void* d_out, int out_size) {
    const float* x    = (const float*)d_in[0];   // [B, T, DIM]
    const float* W    = (const float*)d_in[1];   // [DIM+LATENT, LATENT]
    const float* bias = (const float*)d_in[2];   // [LATENT]
    float* out = (float*)d_out;                  // [T, B, LATENT]

    static int configured = 0;
    if (!configured) {
        cudaFuncSetAttribute(scan_kernel,
                             cudaFuncAttributeMaxDynamicSharedMemorySize, SMEM_SCAN);
        cudaFuncSetAttribute(gemm1_mma_kernel,
                             cudaFuncAttributeMaxDynamicSharedMemorySize, G1_SMEM);
        configured = 1;
    }

    // 0) weight + input splits
    prep_wh_kernel<<<dim3(32, 32), dim3(32, 8)>>>(W);
    prep_bx_kernel<<<dim3(32, 8),  dim3(32, 8)>>>(W);
    prep_x_kernel<<<(BB * TT * DIMK / 4) / 256, 256>>>(x);

    // 1) xw + bias staged into out[t, b, :] (tensor cores)
    gemm1_mma_kernel<<<BB * TT / 128, 256, G1_SMEM>>>(bias, out);

    // 2) t = 0 (+ barrier counter reset)
    tanh0_kernel<<<(BB * TT) / 256 / 2 * 2, 256>>>(out);

    // 3) persistent tensor-core scan for t = 1..511
    scan_kernel<<<NCTA, 256, SMEM_SCAN>>>(out);
}

// round 9
// speedup vs baseline: 1.4063x; 1.4063x over previous
#include <cuda_runtime.h>
#include <cuda_bf16.h>
#include <math.h>
#include <stdint.h>

#define DIMK   256
#define LATENT 1024
#define BB     128
#define TT     512
#define KA     2048          // A' (scan) columns: [hi | lo]
#define KB     2048          // B' (scan) columns: [hi | lo]
#define NCTA   128

// ---------------------------------------------------------------------------
// Scratch (__device__ globals — no allocations allowed)
// ---------------------------------------------------------------------------
__device__ __nv_bfloat16 g_B[LATENT * KB];              // scan B' = WhT split [n][hi1024|lo1024]
__device__ __nv_bfloat16 g_A2[2][BB * KA];              // scan A' ping-pong [m][hi1024|lo1024]
__device__ __nv_bfloat16 g_X[(size_t)BB * TT * 512];    // gemm1 A' = x split [r][hi256|lo256]
__device__ __nv_bfloat16 g_BX[LATENT * 512];            // gemm1 B' = WxT split [n][hi256|lo256]
__device__ unsigned g_bar_m[128];                       // 4 m-group counters, 128B apart

__device__ __forceinline__ uint32_t smem_u32(const void* p) {
    uint32_t a;
    asm("{ .reg .u64 t; cvta.to.shared.u64 t, %1; cvt.u32.u64 %0, t; }" : "=r"(a) : "l"(p));
    return a;
}
__device__ __forceinline__ void cp16(uint32_t dst, const void* src) {
    asm volatile("cp.async.cg.shared.global [%0], [%1], 16;" :: "r"(dst), "l"(src));
}
__device__ __forceinline__ uint32_t pack_hi(float a, float b) {
    __nv_bfloat162 h; h.x = __float2bfloat16(a); h.y = __float2bfloat16(b);
    return *reinterpret_cast<uint32_t*>(&h);
}
__device__ __forceinline__ uint32_t pack_lo(float a, float b) {
    __nv_bfloat16 ha = __float2bfloat16(a), hb = __float2bfloat16(b);
    __nv_bfloat162 l;
    l.x = __float2bfloat16(a - __bfloat162float(ha));
    l.y = __float2bfloat16(b - __bfloat162float(hb));
    return *reinterpret_cast<uint32_t*>(&l);
}
#define CP_COMMIT() asm volatile("cp.async.commit_group;")
#define CP_WAIT(n)  asm volatile("cp.async.wait_group %0;" :: "n"(n))

#define LDSM4(r0, r1, r2, r3, addr) \
    asm volatile("ldmatrix.sync.aligned.m8n8.x4.shared.b16 {%0,%1,%2,%3}, [%4];" \
                 : "=r"(r0), "=r"(r1), "=r"(r2), "=r"(r3) : "r"(addr))
#define MMA16816(d, a0, a1, a2, a3, b0, b1) \
    asm volatile("mma.sync.aligned.m16n8k16.row.col.f32.bf16.bf16.f32 " \
                 "{%0,%1,%2,%3}, {%4,%5,%6,%7}, {%8,%9}, {%0,%1,%2,%3};" \
                 : "+f"((d)[0]), "+f"((d)[1]), "+f"((d)[2]), "+f"((d)[3]) \
                 : "r"(a0), "r"(a1), "r"(a2), "r"(a3), "r"(b0), "r"(b1))

// ---------------------------------------------------------------------------
// prep: Wh[k][n] -> g_B[n][k]=hi, g_B[n][1024+k]=lo
// ---------------------------------------------------------------------------
__global__ void prep_wh_kernel(const float* __restrict__ W) {
    const float* Wh = W + (size_t)DIMK * LATENT;
    __shared__ float tile[32][33];
    int bx = blockIdx.x * 32;
    int by = blockIdx.y * 32;
    int tx = threadIdx.x, ty = threadIdx.y;
    #pragma unroll
    for (int i = ty; i < 32; i += 8)
        tile[i][tx] = Wh[(size_t)(by + i) * LATENT + bx + tx];
    __syncthreads();
    #pragma unroll
    for (int i = ty; i < 32; i += 8) {
        float v = tile[tx][i];
        size_t o = (size_t)(bx + i) * KB + by + tx;
        __nv_bfloat16 h = __float2bfloat16(v);
        g_B[o]        = h;
        g_B[o + 1024] = __float2bfloat16(v - __bfloat162float(h));
    }
}

// ---------------------------------------------------------------------------
// prep: Wx[k][n] (k<256) -> g_BX[n][k]=hi, [n][256+k]=lo
// ---------------------------------------------------------------------------
__global__ void prep_bx_kernel(const float* __restrict__ W) {
    __shared__ float tile[32][33];
    int bx = blockIdx.x * 32;
    int by = blockIdx.y * 32;
    int tx = threadIdx.x, ty = threadIdx.y;
    #pragma unroll
    for (int i = ty; i < 32; i += 8)
        tile[i][tx] = W[(size_t)(by + i) * LATENT + bx + tx];
    __syncthreads();
    #pragma unroll
    for (int i = ty; i < 32; i += 8) {
        float v = tile[tx][i];
        size_t o = (size_t)(bx + i) * 512 + by + tx;
        __nv_bfloat16 h = __float2bfloat16(v);
        g_BX[o]       = h;
        g_BX[o + 256] = __float2bfloat16(v - __bfloat162float(h));
    }
}

// ---------------------------------------------------------------------------
// prep: x[r][d] fp32 -> g_X[r][d]=hi, g_X[r][256+d]=lo  (r = b*T + t)
// ---------------------------------------------------------------------------
__global__ void prep_x_kernel(const float* __restrict__ x) {
    size_t idx = (size_t)blockIdx.x * 256 + threadIdx.x;
    size_t e = idx * 4;
    size_t r = e >> 8;
    int d = (int)(e & 255);
    float4 v = *reinterpret_cast<const float4*>(x + e);
    size_t o = r * 512 + d;
    *reinterpret_cast<uint32_t*>(&g_X[o + 0])   = pack_hi(v.x, v.y);
    *reinterpret_cast<uint32_t*>(&g_X[o + 2])   = pack_hi(v.z, v.w);
    *reinterpret_cast<uint32_t*>(&g_X[o + 256]) = pack_lo(v.x, v.y);
    *reinterpret_cast<uint32_t*>(&g_X[o + 258]) = pack_lo(v.z, v.w);
}

// ---------------------------------------------------------------------------
// GEMM1 (round-6 config verbatim — known 375us): CTA 64 rows, warp tile 32x16,
// A resident 64KB, B double-buffered 2x16KB, 2 CTAs/SM.
// ---------------------------------------------------------------------------
#define G1_SMB   65536
#define G1_SMEM  (65536 + 2 * 16384)

__global__ void __launch_bounds__(256, 2)
gemm1_mma_kernel(const float* __restrict__ bias, float* __restrict__ out) {
    extern __shared__ char smem[];
    const uint32_t smA = smem_u32(smem);
    const uint32_t smB = smA + G1_SMB;
    const int tid = threadIdx.x;
    const int lid = tid & 31;
    const int wid = tid >> 5;
    const int r0 = blockIdx.x * 64;

    {
        const __nv_bfloat16* gA = g_X + (size_t)r0 * 512;
        #pragma unroll
        for (int j = 0; j < 16; ++j) {
            int ci = tid + j * 256;
            int ch = ci >> 10;
            int rem = ci & 1023;
            int rw = rem >> 4;
            int cc = rem & 15;
            cp16(smA + ch * 16384 + rw * 256 + (((cc ^ (rw & 15))) << 4),
                 gA + (size_t)rw * 512 + ch * 128 + cc * 8);
        }
        CP_COMMIT();
    }
    {
        #pragma unroll
        for (int j = 0; j < 4; ++j) {
            int ci = tid + j * 256;
            int rw = ci >> 4;
            int cc = ci & 15;
            cp16(smB + rw * 256 + (((cc ^ (rw & 15))) << 4),
                 g_BX + (size_t)rw * 512 + cc * 8);
        }
        CP_COMMIT();
    }

    const int wm = wid & 1;
    const int wn = wid >> 1;
    const int a_row0 = wm * 32 + (lid & 15);
    const int a_row1 = a_row0 + 16;
    const int a_kh   = (lid >> 4) & 1;
    const int b_row  = wn * 16 + (((lid >> 4) & 1) << 3) + (lid & 7);
    const int b_kh   = (lid >> 3) & 1;
    const int a_swz0 = a_row0 & 15, a_swz1 = a_row1 & 15, b_swz = b_row & 15;
    const int g8 = lid >> 2;
    const int q  = lid & 3;

    float acc[4][4];

    #pragma unroll 1
    for (int gg = 0; gg < 96; ++gg) {
        const int nt = gg / 6;
        const int c  = gg % 6;

        if (gg + 1 < 96) {
            const int nt2 = (gg + 1) / 6;
            const int c2  = (gg + 1) % 6;
            const int cb  = (c2 & 3) * 128;
            uint32_t dst = smB + ((gg + 1) & 1) * 16384;
            const __nv_bfloat16* gBn = g_BX + (size_t)(nt2 * 64) * 512;
            #pragma unroll
            for (int j = 0; j < 4; ++j) {
                int ci = tid + j * 256;
                int rw = ci >> 4;
                int cc = ci & 15;
                cp16(dst + rw * 256 + (((cc ^ (rw & 15))) << 4),
                     gBn + (size_t)rw * 512 + cb + cc * 8);
            }
            CP_COMMIT();
            CP_WAIT(1);
        } else {
            CP_WAIT(0);
        }
        __syncthreads();

        if (c == 0) {
            #pragma unroll
            for (int i = 0; i < 4; ++i)
                #pragma unroll
                for (int j = 0; j < 4; ++j) acc[i][j] = 0.f;
        }

        const int ach = (c < 2) ? c : c - 2;
        const uint32_t aR0 = smA + ach * 16384 + a_row0 * 256;
        const uint32_t aR1 = smA + ach * 16384 + a_row1 * 256;
        const uint32_t bR  = smB + (gg & 1) * 16384 + b_row * 256;

        #pragma unroll
        for (int s = 0; s < 8; ++s) {
            uint32_t A0, A1, A2, A3, C0, C1, C2, C3, B0, B1, B2, B3;
            LDSM4(A0, A1, A2, A3, aR0 + (((2 * s + a_kh) ^ a_swz0) << 4));
            LDSM4(C0, C1, C2, C3, aR1 + (((2 * s + a_kh) ^ a_swz1) << 4));
            LDSM4(B0, B1, B2, B3, bR  + (((2 * s + b_kh) ^ b_swz) << 4));
            MMA16816(acc[0], A0, A1, A2, A3, B0, B1);
            MMA16816(acc[1], A0, A1, A2, A3, B2, B3);
            MMA16816(acc[2], C0, C1, C2, C3, B0, B1);
            MMA16816(acc[3], C0, C1, C2, C3, B2, B3);
        }

        if (c == 5) {
            const int n0 = nt * 64;
            #pragma unroll
            for (int f = 0; f < 2; ++f) {
                #pragma unroll
                for (int ntf = 0; ntf < 2; ++ntf) {
                    const int col = n0 + wn * 16 + ntf * 8 + q * 2;
                    float2 bv = *reinterpret_cast<const float2*>(bias + col);
                    #pragma unroll
                    for (int rh = 0; rh < 2; ++rh) {
                        const int r = r0 + wm * 32 + f * 16 + g8 + rh * 8;
                        const int bi = r >> 9;
                        const int ti = r & (TT - 1);
                        float2 o;
                        o.x = acc[f * 2 + ntf][rh * 2 + 0] + bv.x;
                        o.y = acc[f * 2 + ntf][rh * 2 + 1] + bv.y;
                        *reinterpret_cast<float2*>(
                            &out[((size_t)ti * BB + bi) * LATENT + col]) = o;
                    }
                }
            }
        }
        __syncthreads();
    }
}

// ---------------------------------------------------------------------------
// t = 0: out[0] = tanh(out[0]); split h0 into g_A2[0]; reset m-group barriers
// ---------------------------------------------------------------------------
__global__ void tanh0_kernel(float* __restrict__ out0) {
    int i = blockIdx.x * blockDim.x + threadIdx.x;
    if (i < 4) g_bar_m[i * 32] = 0;
    int m = i >> 10;
    int k = i & 1023;
    float v = tanhf(out0[i]);
    out0[i] = v;
    __nv_bfloat16 h = __float2bfloat16(v);
    size_t o = (size_t)m * KA + k;
    g_A2[0][o]        = h;
    g_A2[0][o + 1024] = __float2bfloat16(v - __bfloat162float(h));
}

// ---------------------------------------------------------------------------
// Persistent scan: 128 CTAs (4m x 32n tiles of 32x32), 256 threads = 8 warps.
// 8-way split-K: warp w owns k-chunk w (128 cols), full 32x32 tile, 3 terms
// (Ahi*Bhi + Ahi*Blo + Alo*Bhi). B-hi fragments REGISTER-RESIDENT (loaded once,
// constant across all steps); B-lo resident in smem (64KB). A: each warp
// self-stages its own 16KB chunk per step (cp.async, no cross-warp barriers).
// Partials exchanged in reused A smem; per-m-group grid barrier (32 CTAs).
// ---------------------------------------------------------------------------
#define SCAN_BLO  65536                       // B-lo: 8 chunks x 8KB
#define SCAN_A    65536                       // A region: 8 chunks x 16KB (reused: partials)
#define SMEM_SCAN (65536 + 131072)            // 196608

__global__ void __launch_bounds__(256, 1)
scan_kernel(float* __restrict__ out) {
    extern __shared__ char smem[];
    const int tid = threadIdx.x;
    const int lid = tid & 31;
    const int wid = tid >> 5;
    const int bid = blockIdx.x;
    const int mg = bid & 3;
    const int m0 = mg * 32;
    const int n0 = (bid >> 2) * 32;
    const uint32_t smB = smem_u32(smem);
    const uint32_t smA = smB + SCAN_A;
    const uint32_t abase = smA + wid * 16384;     // this warp's A chunk slot

    // ---- B geometry ----
    const int b_r  = (((lid >> 4) & 1) << 3) + (lid & 7);
    const int b_kh = (lid >> 3) & 1;
    const int b_swz = b_r & 15;
    // ---- A geometry (m-frag rows 0-15 and 16-31) ----
    const int a_r  = lid & 15;
    const int a_kh = (lid >> 4) & 1;
    const int a_swz = a_r & 15;

    // ---- init: warp w stages B-lo chunk w (resident) + B-hi chunk w (temp) ----
    {
        const __nv_bfloat16* gB = g_B + (size_t)n0 * KB;
        #pragma unroll
        for (int j = 0; j < 16; ++j) {
            int ci = lid + j * 32;        // 0..511
            int rw = ci >> 4;
            int cc = ci & 15;
            uint32_t sw = ((cc ^ (rw & 15)) << 4);
            cp16(smB + wid * 8192 + rw * 256 + sw,
                 gB + (size_t)rw * KB + 1024 + wid * 128 + cc * 8);   // lo
            cp16(abase + rw * 256 + sw,
                 gB + (size_t)rw * KB + wid * 128 + cc * 8);          // hi (temp)
        }
        CP_COMMIT();
        CP_WAIT(0);
        __syncwarp();
    }

    // ---- load B-hi fragments into registers (constant for all 511 steps) ----
    uint32_t bhi[8][8];
    #pragma unroll
    for (int s = 0; s < 8; ++s) {
        const uint32_t off = ((uint32_t)((2 * s + b_kh) ^ b_swz)) << 4;
        LDSM4(bhi[s][0], bhi[s][1], bhi[s][2], bhi[s][3], abase + b_r * 256 + off);
        LDSM4(bhi[s][4], bhi[s][5], bhi[s][6], bhi[s][7], abase + (b_r + 16) * 256 + off);
    }
    __syncwarp();

    // ---- epilogue geometry ----
    const int e_row = tid >> 3;            // 0..31
    const int e_cg  = (tid & 7) * 4;       // 0..28
    const int gm = m0 + e_row;
    const int e0 = n0 + e_cg;
    volatile unsigned* barp = &g_bar_m[mg * 32];

    for (int t = 1; t < TT; ++t) {
        const int rp = (t - 1) & 1;
        const __nv_bfloat16* Ar = g_A2[rp] + (size_t)m0 * KA;
        __nv_bfloat16* Aw = g_A2[rp ^ 1];
        float* out_t = out + (size_t)t * BB * LATENT;

        // ---- warp self-stage: its A chunk (hi 8KB + lo 8KB) ----
        #pragma unroll
        for (int j = 0; j < 32; ++j) {
            int ci = lid + j * 32;            // 0..1023
            int half = ci >> 9;
            int rem = ci & 511;
            int rw = rem >> 4;
            int cc = rem & 15;
            cp16(abase + half * 8192 + rw * 256 + ((cc ^ (rw & 15)) << 4),
                 Ar + (size_t)rw * KA + half * 1024 + wid * 128 + cc * 8);
        }
        CP_COMMIT();

        // ---- xw prefetch (hidden under staging wait + MMA) ----
        const float4 xv = *reinterpret_cast<const float4*>(
            out_t + (size_t)gm * LATENT + e0);

        CP_WAIT(0);
        __syncwarp();

        float acc[32];
        #pragma unroll
        for (int i = 0; i < 32; ++i) acc[i] = 0.f;

        const uint32_t aH = abase + a_r * 256;
        const uint32_t aL = abase + 8192 + a_r * 256;
        const uint32_t bLo = smB + wid * 8192 + b_r * 256;

        #pragma unroll
        for (int s = 0; s < 8; ++s) {
            const uint32_t aoff = ((uint32_t)((2 * s + a_kh) ^ a_swz)) << 4;
            const uint32_t boff = ((uint32_t)((2 * s + b_kh) ^ b_swz)) << 4;
            uint32_t AH0[4], AH1[4], AL0[4], AL1[4], blo[8];
            LDSM4(AH0[0], AH0[1], AH0[2], AH0[3], aH + aoff);
            LDSM4(AH1[0], AH1[1], AH1[2], AH1[3], aH + 4096 + aoff);
            LDSM4(AL0[0], AL0[1], AL0[2], AL0[3], aL + aoff);
            LDSM4(AL1[0], AL1[1], AL1[2], AL1[3], aL + 4096 + aoff);
            LDSM4(blo[0], blo[1], blo[2], blo[3], bLo + boff);
            LDSM4(blo[4], blo[5], blo[6], blo[7], bLo + 16 * 256 + boff);

            #pragma unroll
            for (int ni = 0; ni < 4; ++ni) {
                MMA16816(acc + ni * 4, AH0[0], AH0[1], AH0[2], AH0[3],
                         bhi[s][ni * 2], bhi[s][ni * 2 + 1]);
                MMA16816(acc + ni * 4, AH0[0], AH0[1], AH0[2], AH0[3],
                         blo[ni * 2], blo[ni * 2 + 1]);
                MMA16816(acc + ni * 4, AL0[0], AL0[1], AL0[2], AL0[3],
                         bhi[s][ni * 2], bhi[s][ni * 2 + 1]);
                MMA16816(acc + 16 + ni * 4, AH1[0], AH1[1], AH1[2], AH1[3],
                         bhi[s][ni * 2], bhi[s][ni * 2 + 1]);
                MMA16816(acc + 16 + ni * 4, AH1[0], AH1[1], AH1[2], AH1[3],
                         blo[ni * 2], blo[ni * 2 + 1]);
                MMA16816(acc + 16 + ni * 4, AL1[0], AL1[1], AL1[2], AL1[3],
                         bhi[s][ni * 2], bhi[s][ni * 2 + 1]);
            }
        }

        // ---- exchange partials (A region reused; all A reads done) ----
        __syncthreads();
        {
            char* pb = smem + SCAN_A + wid * 4608;
            #pragma unroll
            for (int mi = 0; mi < 2; ++mi)
                #pragma unroll
                for (int ni = 0; ni < 4; ++ni)
                    #pragma unroll
                    for (int rh = 0; rh < 2; ++rh) {
                        const int r_l = mi * 16 + (lid >> 2) + rh * 8;
                        const int c_l = ni * 8 + (lid & 3) * 2;
                        float2 pv;
                        pv.x = acc[mi * 16 + ni * 4 + rh * 2 + 0];
                        pv.y = acc[mi * 16 + ni * 4 + rh * 2 + 1];
                        *reinterpret_cast<float2*>(pb + (r_l * 36 + c_l) * 4) = pv;
                    }
        }
        __syncthreads();

        // ---- reduce 8 partials + tanh; write out + A' (row layout, coalesced) ----
        {
            float4 s4 = xv;
            #pragma unroll
            for (int w = 0; w < 8; ++w) {
                const float4 pv = *reinterpret_cast<const float4*>(
                    smem + SCAN_A + w * 4608 + (e_row * 36 + e_cg) * 4);
                s4.x += pv.x; s4.y += pv.y; s4.z += pv.z; s4.w += pv.w;
            }
            float4 r;
            r.x = tanhf(s4.x);
            r.y = tanhf(s4.y);
            r.z = tanhf(s4.z);
            r.w = tanhf(s4.w);
            *reinterpret_cast<float4*>(out_t + (size_t)gm * LATENT + e0) = r;

            const size_t ao = (size_t)gm * KA + e0;
            *reinterpret_cast<uint32_t*>(Aw + ao + 0)    = pack_hi(r.x, r.y);
            *reinterpret_cast<uint32_t*>(Aw + ao + 2)    = pack_hi(r.z, r.w);
            *reinterpret_cast<uint32_t*>(Aw + ao + 1024) = pack_lo(r.x, r.y);
            *reinterpret_cast<uint32_t*>(Aw + ao + 1026) = pack_lo(r.z, r.w);
        }

        // ---- per-m-group barrier (32 CTAs) ----
        if (t + 1 < TT) {
            __threadfence();
            __syncthreads();
            if (tid == 0) {
                atomicAdd((unsigned*)barp, 1u);
                const unsigned target = (unsigned)t * 32;
                while (*barp < target) { }
            }
            __syncthreads();
        }
    }
}

// ---------------------------------------------------------------------------
extern "C" void kernel_launch(void* const* d_in, const int* in_sizes, int n_in,
                              void* d_out, int out_size) {
    const float* x    = (const float*)d_in[0];   // [B, T, DIM]
    const float* W    = (const float*)d_in[1];   // [DIM+LATENT, LATENT]
    const float* bias = (const float*)d_in[2];   // [LATENT]
    float* out = (float*)d_out;                  // [T, B, LATENT]

    static int configured = 0;
    if (!configured) {
        cudaFuncSetAttribute(scan_kernel,
                             cudaFuncAttributeMaxDynamicSharedMemorySize, SMEM_SCAN);
        cudaFuncSetAttribute(gemm1_mma_kernel,
                             cudaFuncAttributeMaxDynamicSharedMemorySize, G1_SMEM);
        configured = 1;
    }

    // 0) weight + input splits
    prep_wh_kernel<<<dim3(32, 32), dim3(32, 8)>>>(W);
    prep_bx_kernel<<<dim3(32, 8),  dim3(32, 8)>>>(W);
    prep_x_kernel<<<(BB * TT * DIMK / 4) / 256, 256>>>(x);

    // 1) xw + bias staged into out[t, b, :] (tensor cores, 2 CTAs/SM)
    gemm1_mma_kernel<<<BB * TT / 64, 256, G1_SMEM>>>(bias, out);

    // 2) t = 0 (+ barrier counter reset)
    tanh0_kernel<<<(BB * LATENT) / 256, 256>>>(out);

    // 3) persistent tensor-core scan for t = 1..511
    scan_kernel<<<NCTA, 256, SMEM_SCAN>>>(out);
}